// round 1
// baseline (speedup 1.0000x reference)
#include <cuda_runtime.h>
#include <cstdint>
#include <cstddef>

#define BATCH 4
#define ZCH 64
#define ED 16
#define NEMB 16384
#define PCH 64
#define FRES 32
#define NPOS (BATCH*FRES*FRES)
#define NBT (NEMB/128)

__device__ float g_z[NPOS*ED];
__device__ float g_zz[NPOS];
__device__ float g_cnorm[NEMB];
__device__ float g_zl[BATCH*ED*FRES*FRES];
__device__ float g_h[NPOS*PCH];
__device__ float g_pv[(size_t)NPOS*NBT];
__device__ int   g_pi[(size_t)NPOS*NBT];
__device__ float g_pv2[(size_t)NPOS*NBT];
__device__ int   g_pi2[(size_t)NPOS*NBT];
__device__ int   g_vqidx[NPOS];
__device__ int   g_topidx[NPOS];
__device__ float g_dcin[BATCH*ZCH*FRES*FRES];
__device__ float g_d0[BATCH*ZCH*FRES*FRES];
__device__ float g_t[BATCH*ZCH*64*64];

__device__ __forceinline__ float get_w(const void* wp) {
    int i = *(const int*)wp;
    float f = __int_as_float(i);
    float af = fabsf(f);
    if (af < 1e-20f) return (float)i;
    if (i > -100000000 && i < 100000000) return (float)i;
    return f;
}

__global__ void k_cnorm(const float* __restrict__ cb) {
    int n = blockIdx.x * 256 + threadIdx.x;
    if (n < NEMB) {
        const float* r = cb + (size_t)n * ED;
        float s = 0.f;
        #pragma unroll
        for (int e = 0; e < ED; e++) s += r[e] * r[e];
        g_cnorm[n] = s;
    }
}

__global__ void __launch_bounds__(256) k_quant_lrq(
    const float* __restrict__ zt, const float* __restrict__ zlp,
    const float* __restrict__ qw, const float* __restrict__ qb,
    const float* __restrict__ lw, const float* __restrict__ lb,
    float* __restrict__ out_zl)
{
    __shared__ float sqw[ED*ZCH];
    __shared__ float slw[ED*ZCH];
    int tid = threadIdx.x;
    for (int i = tid; i < ED*ZCH; i += 256) { sqw[i] = qw[i]; slw[i] = lw[i]; }
    __syncthreads();
    int p = blockIdx.x * 256 + tid;
    int b = p >> 10, rem = p & 1023;
    float q[ED], l[ED];
    #pragma unroll
    for (int e = 0; e < ED; e++) { q[e] = qb[e]; l[e] = lb[e]; }
    size_t base = (size_t)b * ZCH * 1024 + rem;
    for (int c = 0; c < ZCH; c++) {
        float a  = zt[base + (size_t)c * 1024];
        float zl = zlp[base + (size_t)c * 1024];
        #pragma unroll
        for (int e = 0; e < ED; e++) {
            q[e] = fmaf(a,  sqw[e*ZCH + c], q[e]);
            l[e] = fmaf(zl, slw[e*ZCH + c], l[e]);
        }
    }
    float zz = 0.f;
    #pragma unroll
    for (int e = 0; e < ED; e++) { g_z[(size_t)p*ED + e] = q[e]; zz = fmaf(q[e], q[e], zz); }
    g_zz[p] = zz;
    #pragma unroll
    for (int e = 0; e < ED; e++) {
        size_t oi = (size_t)b * ED * 1024 + (size_t)e * 1024 + rem;
        out_zl[oi] = l[e];
        g_zl[oi]  = l[e];
    }
}

// MODE 0: logits = h @ W^T + bias, write C, per-tile argmax partials
// MODE 1: d = zz + cnorm - 2 * z @ cb^T, per-tile argmin partials (nvec ignored, reads g_cnorm)
template<int KDIM, int MODE>
__global__ void __launch_bounds__(256, 2) k_gemm(
    const float* __restrict__ Bm,
    const float* __restrict__ nvec,
    float* __restrict__ C)
{
    __shared__ float As[16][128];
    __shared__ float Bs[16][128];
    const float* Am = (MODE == 0) ? g_h : g_z;
    const int n0 = blockIdx.x * 128;
    const int m0 = blockIdx.y * 128;
    const int tid = threadIdx.x;
    const int tx = tid & 15, ty = tid >> 4;
    float acc[8][8];
    #pragma unroll
    for (int i = 0; i < 8; i++)
        #pragma unroll
        for (int j = 0; j < 8; j++) acc[i][j] = 0.f;

    for (int kt = 0; kt < KDIM; kt += 16) {
        #pragma unroll
        for (int q = 0; q < 2; q++) {
            int e4 = tid + q * 256;
            int row = e4 >> 2;
            int kq = (e4 & 3) << 2;
            float4 va = *(const float4*)(Am + (size_t)(m0 + row) * KDIM + kt + kq);
            As[kq+0][row] = va.x; As[kq+1][row] = va.y; As[kq+2][row] = va.z; As[kq+3][row] = va.w;
            float4 vb = *(const float4*)(Bm + (size_t)(n0 + row) * KDIM + kt + kq);
            Bs[kq+0][row] = vb.x; Bs[kq+1][row] = vb.y; Bs[kq+2][row] = vb.z; Bs[kq+3][row] = vb.w;
        }
        __syncthreads();
        #pragma unroll
        for (int k = 0; k < 16; k++) {
            float a[8], bb[8];
            #pragma unroll
            for (int i = 0; i < 8; i++) a[i] = As[k][ty*8 + i];
            #pragma unroll
            for (int j = 0; j < 8; j++) bb[j] = Bs[k][tx*8 + j];
            #pragma unroll
            for (int i = 0; i < 8; i++)
                #pragma unroll
                for (int j = 0; j < 8; j++) acc[i][j] = fmaf(a[i], bb[j], acc[i][j]);
        }
        __syncthreads();
    }

    float nv[8];
    #pragma unroll
    for (int j = 0; j < 8; j++)
        nv[j] = (MODE == 0) ? nvec[n0 + tx*8 + j] : g_cnorm[n0 + tx*8 + j];
    float lv[8]; int li[8];
    #pragma unroll
    for (int i = 0; i < 8; i++) {
        int gr = m0 + ty*8 + i;
        float best; int bidx = n0 + tx*8;
        if (MODE == 0) {
            float v[8];
            #pragma unroll
            for (int j = 0; j < 8; j++) v[j] = acc[i][j] + nv[j];
            float4* cp = (float4*)(C + (size_t)gr * NEMB + n0 + tx*8);
            cp[0] = make_float4(v[0], v[1], v[2], v[3]);
            cp[1] = make_float4(v[4], v[5], v[6], v[7]);
            best = v[0];
            #pragma unroll
            for (int j = 1; j < 8; j++) if (v[j] > best) { best = v[j]; bidx = n0 + tx*8 + j; }
        } else {
            float zz = g_zz[gr];
            float v[8];
            #pragma unroll
            for (int j = 0; j < 8; j++) v[j] = zz + nv[j] - 2.f * acc[i][j];
            best = v[0];
            #pragma unroll
            for (int j = 1; j < 8; j++) if (v[j] < best) { best = v[j]; bidx = n0 + tx*8 + j; }
        }
        lv[i] = best; li[i] = bidx;
    }
    __syncthreads();
    float* sval = &As[0][0];
    int*   sidx = (int*)&Bs[0][0];
    #pragma unroll
    for (int i = 0; i < 8; i++) { int row = ty*8 + i; sval[row*16 + tx] = lv[i]; sidx[row*16 + tx] = li[i]; }
    __syncthreads();
    if (tid < 128) {
        float bv = sval[tid*16]; int bi = sidx[tid*16];
        #pragma unroll
        for (int t = 1; t < 16; t++) {
            float v = sval[tid*16 + t]; int ii = sidx[tid*16 + t];
            bool better = (MODE == 0) ? (v > bv) : (v < bv);
            if (better || (v == bv && ii < bi)) { bv = v; bi = ii; }
        }
        size_t o = (size_t)(m0 + tid) * NBT + blockIdx.x;
        if (MODE == 0) { g_pv[o] = bv;  g_pi[o] = bi; }
        else           { g_pv2[o] = bv; g_pi2[o] = bi; }
    }
}

template<bool ISMAX>
__global__ void k_argreduce(float* __restrict__ outf) {
    int row = blockIdx.x, t = threadIdx.x;
    __shared__ float sv[128];
    __shared__ int   si[128];
    const float* pv = ISMAX ? g_pv : g_pv2;
    const int*   pi = ISMAX ? g_pi : g_pi2;
    sv[t] = pv[(size_t)row * NBT + t];
    si[t] = pi[(size_t)row * NBT + t];
    __syncthreads();
    for (int s = 64; s; s >>= 1) {
        if (t < s) {
            float v2 = sv[t+s]; int i2 = si[t+s];
            bool better = ISMAX ? (v2 > sv[t]) : (v2 < sv[t]);
            if (better || (v2 == sv[t] && i2 < si[t])) { sv[t] = v2; si[t] = i2; }
        }
        __syncthreads();
    }
    if (t == 0) {
        if (ISMAX) g_topidx[row] = si[0];
        else { g_vqidx[row] = si[0]; outf[row] = (float)si[0]; }
    }
}

__global__ void k_zhq(const float* __restrict__ cb, float* __restrict__ out_zhq) {
    int o = blockIdx.x * 256 + threadIdx.x;
    int b = o >> 14, e = (o >> 10) & 15, rem = o & 1023;
    int p = b * 1024 + rem;
    out_zhq[o] = cb[(size_t)g_vqidx[p] * ED + e];
}

__global__ void __launch_bounds__(256) k_pcn1(const float* __restrict__ w1, const float* __restrict__ b1) {
    __shared__ float img[8 * 1024];
    __shared__ float wt[ED * 49];
    int b = blockIdx.x >> 6, oc = blockIdx.x & 63;
    int tid = threadIdx.x;
    for (int i = tid; i < ED * 49; i += 256) wt[i] = w1[(size_t)oc * ED * 49 + i];
    float bias = b1[oc];
    float acc[4];
    #pragma unroll
    for (int k = 0; k < 4; k++) acc[k] = bias;
    for (int half = 0; half < 2; half++) {
        __syncthreads();
        for (int i = tid; i < 8192; i += 256) img[i] = g_zl[(size_t)b * 16384 + half * 8192 + i];
        __syncthreads();
        #pragma unroll
        for (int k = 0; k < 4; k++) {
            int p = tid + k * 256;
            int y = p >> 5, x = p & 31;
            for (int ic = 0; ic < 8; ic++) {
                const float* ib = img + ic * 1024;
                const float* wb = wt + (half * 8 + ic) * 49;
                #pragma unroll
                for (int ky = 0; ky < 7; ky++) {
                    int yy = y + ky - 3;
                    if (yy < 0 || yy >= 32) continue;
                    #pragma unroll
                    for (int kx = 0; kx < 7; kx++) {
                        int xx = x + kx - 3;
                        if (xx < 0 || xx >= 32) continue;
                        acc[k] = fmaf(ib[yy*32 + xx], wb[ky*7 + kx], acc[k]);
                    }
                }
            }
        }
    }
    #pragma unroll
    for (int k = 0; k < 4; k++) {
        int p = tid + k * 256;
        g_h[(size_t)(b * 1024 + p) * PCH + oc] = fmaxf(acc[k], 0.f);
    }
}

__global__ void __launch_bounds__(256) k_pq(const float* __restrict__ cb,
                                            const float* __restrict__ pqw,
                                            const float* __restrict__ pqb) {
    __shared__ float spw[ZCH * ED];
    int tid = threadIdx.x;
    for (int i = tid; i < ZCH * ED; i += 256) spw[i] = pqw[i];
    __syncthreads();
    int p = blockIdx.x * 256 + tid;
    int b = p >> 10, rem = p & 1023;
    float code[ED];
    int ci = g_topidx[p];
    #pragma unroll
    for (int e = 0; e < ED; e++) code[e] = cb[(size_t)ci * ED + e];
    for (int zc = 0; zc < ZCH; zc++) {
        float a = pqb[zc];
        #pragma unroll
        for (int e = 0; e < ED; e++) a = fmaf(spw[zc*ED + e], code[e], a);
        g_dcin[(size_t)b * ZCH * 1024 + (size_t)zc * 1024 + rem] = a;
    }
}

__global__ void __launch_bounds__(256) k_dec1(const float* __restrict__ w, const float* __restrict__ bias) {
    __shared__ float slice[1024];
    int b = blockIdx.x >> 6, oc = blockIdx.x & 63;
    int tid = threadIdx.x;
    float bb = bias[oc];
    float acc[4];
    #pragma unroll
    for (int k = 0; k < 4; k++) acc[k] = bb;
    for (int ic = 0; ic < ZCH; ic++) {
        __syncthreads();
        for (int i = tid; i < 1024; i += 256) slice[i] = g_dcin[(size_t)b * 65536 + (size_t)ic * 1024 + i];
        __syncthreads();
        float w9[9];
        #pragma unroll
        for (int j = 0; j < 9; j++) w9[j] = w[((size_t)oc * ZCH + ic) * 9 + j];
        #pragma unroll
        for (int k = 0; k < 4; k++) {
            int p = tid + k * 256;
            int y = p >> 5, x = p & 31;
            #pragma unroll
            for (int ky = 0; ky < 3; ky++) {
                int yy = y + ky - 1;
                if (yy < 0 || yy >= 32) continue;
                #pragma unroll
                for (int kx = 0; kx < 3; kx++) {
                    int xx = x + kx - 1;
                    if (xx < 0 || xx >= 32) continue;
                    acc[k] = fmaf(slice[yy*32 + xx], w9[ky*3 + kx], acc[k]);
                }
            }
        }
    }
    #pragma unroll
    for (int k = 0; k < 4; k++)
        g_d0[(size_t)b * 65536 + (size_t)oc * 1024 + tid + k * 256] = fmaxf(acc[k], 0.f);
}

__global__ void __launch_bounds__(256) k_fuse(const float* __restrict__ ff,
                                              const float* __restrict__ fw,
                                              const float* __restrict__ fb,
                                              const void* __restrict__ wscalar) {
    __shared__ float slice[64 * 64];
    int b = blockIdx.x >> 6, oc = blockIdx.x & 63;
    int tid = threadIdx.x;
    int ty0 = (tid >> 4) * 4, tx0 = (tid & 15) * 4;
    float acc[4][4];
    float bb = fb[oc];
    #pragma unroll
    for (int i = 0; i < 4; i++)
        #pragma unroll
        for (int j = 0; j < 4; j++) acc[i][j] = bb;
    for (int ic = 0; ic < ZCH; ic++) {
        __syncthreads();
        for (int i = tid; i < 4096; i += 256)
            slice[i] = ff[(size_t)b * ZCH * 4096 + (size_t)ic * 4096 + i];
        __syncthreads();
        float w9[9];
        #pragma unroll
        for (int j = 0; j < 9; j++) w9[j] = fw[((size_t)oc * ZCH + ic) * 9 + j];
        float r[6][6];
        #pragma unroll
        for (int yy = 0; yy < 6; yy++)
            #pragma unroll
            for (int xx = 0; xx < 6; xx++) {
                int Y = ty0 + yy - 1, X = tx0 + xx - 1;
                r[yy][xx] = (Y >= 0 && Y < 64 && X >= 0 && X < 64) ? slice[Y*64 + X] : 0.f;
            }
        #pragma unroll
        for (int i = 0; i < 4; i++)
            #pragma unroll
            for (int j = 0; j < 4; j++)
                #pragma unroll
                for (int ky = 0; ky < 3; ky++)
                    #pragma unroll
                    for (int kx = 0; kx < 3; kx++)
                        acc[i][j] = fmaf(r[i+ky][j+kx], w9[ky*3 + kx], acc[i][j]);
    }
    float wf = get_w(wscalar);
    #pragma unroll
    for (int i = 0; i < 4; i++)
        #pragma unroll
        for (int j = 0; j < 4; j++) {
            int Y = ty0 + i, X = tx0 + j;
            float v = g_d0[(size_t)b * 65536 + (size_t)oc * 1024 + (Y>>1)*32 + (X>>1)] + wf * acc[i][j];
            g_t[(size_t)b * ZCH * 4096 + (size_t)oc * 4096 + Y*64 + X] = fmaxf(v, 0.f);
        }
}

__global__ void __launch_bounds__(256) k_dec2(const float* __restrict__ w2,
                                              const float* __restrict__ b2,
                                              float* __restrict__ out_dec) {
    __shared__ float rows[3][64];
    int b = blockIdx.x >> 6;
    int Y0 = (blockIdx.x & 63) * 2;
    int tid = threadIdx.x;
    int Y = Y0 + (tid >> 7);
    int X = tid & 127;
    int m = Y0 >> 1;
    float acc = b2[0];
    for (int c = 0; c < ZCH; c++) {
        __syncthreads();
        for (int i = tid; i < 192; i += 256) {
            int rr = i / 64, cc = i % 64;
            int tr = m - 1 + rr;
            rows[rr][cc] = (tr >= 0 && tr < 64)
                ? g_t[(size_t)b * ZCH * 4096 + (size_t)c * 4096 + tr*64 + cc] : 0.f;
        }
        __syncthreads();
        float w9[9];
        #pragma unroll
        for (int j = 0; j < 9; j++) w9[j] = w2[(size_t)c * 9 + j];
        #pragma unroll
        for (int ky = 0; ky < 3; ky++) {
            int Yt = Y + ky - 1;
            if (Yt < 0 || Yt > 127) continue;
            int rr = (Yt >> 1) - (m - 1);
            #pragma unroll
            for (int kx = 0; kx < 3; kx++) {
                int Xt = X + kx - 1;
                if (Xt < 0 || Xt > 127) continue;
                acc = fmaf(rows[rr][Xt >> 1], w9[ky*3 + kx], acc);
            }
        }
    }
    out_dec[(size_t)b * 16384 + Y * 128 + X] = acc;
}

extern "C" void kernel_launch(void* const* d_in, const int* in_sizes, int n_in,
                              void* d_out, int out_size) {
    const float* z_t      = (const float*)d_in[0];
    const float* z_l_pre  = (const float*)d_in[1];
    const float* fuse_feat= (const float*)d_in[2];
    const void*  wptr     = d_in[3];
    const float* quant_w  = (const float*)d_in[4];
    const float* quant_b  = (const float*)d_in[5];
    const float* codebook = (const float*)d_in[6];
    const float* lrq_w    = (const float*)d_in[7];
    const float* lrq_b    = (const float*)d_in[8];
    const float* pcn_w1   = (const float*)d_in[9];
    const float* pcn_b1   = (const float*)d_in[10];
    const float* pcn_w2   = (const float*)d_in[11];
    const float* pcn_b2   = (const float*)d_in[12];
    const float* pq_w     = (const float*)d_in[13];
    const float* pq_b     = (const float*)d_in[14];
    const float* dec_w1   = (const float*)d_in[15];
    const float* dec_b1   = (const float*)d_in[16];
    const float* fuse_w   = (const float*)d_in[17];
    const float* fuse_b   = (const float*)d_in[18];
    const float* dec_w2   = (const float*)d_in[19];
    const float* dec_b2   = (const float*)d_in[20];

    float* out = (float*)d_out;
    float* out_logits = out;
    float* out_zl     = out_logits + (size_t)NPOS * NEMB;
    float* out_tgt    = out_zl + (size_t)BATCH * ED * 1024;
    float* out_zhq    = out_tgt + NPOS;
    float* out_dec    = out_zhq + (size_t)BATCH * ED * 1024;

    k_cnorm<<<NEMB/256, 256>>>(codebook);
    k_quant_lrq<<<NPOS/256, 256>>>(z_t, z_l_pre, quant_w, quant_b, lrq_w, lrq_b, out_zl);

    // frozen HQ path: VQ argmin + gather
    k_gemm<16, 1><<<dim3(NBT, NPOS/128), 256>>>(codebook, nullptr, nullptr);
    k_argreduce<false><<<NPOS, 128>>>(out_tgt);
    k_zhq<<<(BATCH*ED*1024)/256, 256>>>(codebook, out_zhq);

    // LR path: pixelcnn + logits + argmax
    k_pcn1<<<BATCH*PCH, 256>>>(pcn_w1, pcn_b1);
    k_gemm<64, 0><<<dim3(NBT, NPOS/128), 256>>>(pcn_w2, pcn_b2, out_logits);
    k_argreduce<true><<<NPOS, 128>>>(nullptr);

    // decoder
    k_pq<<<NPOS/256, 256>>>(codebook, pq_w, pq_b);
    k_dec1<<<BATCH*ZCH, 256>>>(dec_w1, dec_b1);
    k_fuse<<<BATCH*ZCH, 256>>>(fuse_feat, fuse_w, fuse_b, wptr);
    k_dec2<<<BATCH*64, 256>>>(dec_w2, dec_b2, out_dec);
}

// round 3
// speedup vs baseline: 1.1737x; 1.1737x over previous
#include <cuda_runtime.h>
#include <cuda_bf16.h>
#include <cstdint>
#include <cstddef>

#define BATCH 4
#define ZCH 64
#define ED 16
#define NEMB 16384
#define PCH 64
#define FRES 32
#define NPOS (BATCH*FRES*FRES)
#define NBT (NEMB/128)
#define KSPLIT 192     // 3 x 64 concatenated bf16 split planes

// ---------------- scratch ----------------
__device__ float g_z[NPOS*ED];
__device__ float g_zz[NPOS];
__device__ float g_cnorm[NEMB];
__device__ float g_zl[BATCH*ED*FRES*FRES];
__device__ float g_h[NPOS*PCH];
__device__ float g_pv[(size_t)NPOS*NBT];
__device__ int   g_pi[(size_t)NPOS*NBT];
__device__ float g_pv2[(size_t)NPOS*NBT];
__device__ int   g_pi2[(size_t)NPOS*NBT];
__device__ int   g_vqidx[NPOS];
__device__ int   g_topidx[NPOS];
__device__ float g_dcin[BATCH*ZCH*FRES*FRES];
__device__ float g_d0[BATCH*ZCH*FRES*FRES];
__device__ float g_t[BATCH*ZCH*64*64];
// K-interleaved bf16 split: A row = [hi(64) | hi(64) | lo(64)], B row = [hi | lo | hi]
__device__ __align__(16) __nv_bfloat16 g_Ab[(size_t)NPOS*KSPLIT];
__device__ __align__(16) __nv_bfloat16 g_Bb[(size_t)NEMB*KSPLIT];

__device__ __forceinline__ uint32_t smem_to_u32(const void* p) {
    uint32_t a;
    asm("{ .reg .u64 t; cvta.to.shared.u64 t, %1; cvt.u32.u64 %0, t; }" : "=r"(a) : "l"(p));
    return a;
}
__device__ __forceinline__ void ldsm_x4(uint32_t& r0, uint32_t& r1, uint32_t& r2, uint32_t& r3, uint32_t addr) {
    asm volatile("ldmatrix.sync.aligned.m8n8.x4.shared.b16 {%0,%1,%2,%3}, [%4];"
                 : "=r"(r0), "=r"(r1), "=r"(r2), "=r"(r3) : "r"(addr));
}
__device__ __forceinline__ void mma16816(float* c, const uint32_t* a, const uint32_t* b) {
    asm volatile("mma.sync.aligned.m16n8k16.row.col.f32.bf16.bf16.f32 "
                 "{%0,%1,%2,%3}, {%4,%5,%6,%7}, {%8,%9}, {%0,%1,%2,%3};"
                 : "+f"(c[0]), "+f"(c[1]), "+f"(c[2]), "+f"(c[3])
                 : "r"(a[0]), "r"(a[1]), "r"(a[2]), "r"(a[3]), "r"(b[0]), "r"(b[1]));
}

__device__ __forceinline__ float get_w(const void* wp) {
    int i = *(const int*)wp;
    float f = __int_as_float(i);
    float af = fabsf(f);
    if (af < 1e-20f) return (float)i;
    if (i > -100000000 && i < 100000000) return (float)i;
    return f;
}

// ---------------- simple kernels ----------------
__global__ void k_cnorm(const float* __restrict__ cb) {
    int n = blockIdx.x * 256 + threadIdx.x;
    if (n < NEMB) {
        const float* r = cb + (size_t)n * ED;
        float s = 0.f;
        #pragma unroll
        for (int e = 0; e < ED; e++) s += r[e] * r[e];
        g_cnorm[n] = s;
    }
}

__global__ void __launch_bounds__(256) k_quant_lrq(
    const float* __restrict__ zt, const float* __restrict__ zlp,
    const float* __restrict__ qw, const float* __restrict__ qb,
    const float* __restrict__ lw, const float* __restrict__ lb,
    float* __restrict__ out_zl)
{
    __shared__ float sqw[ED*ZCH];
    __shared__ float slw[ED*ZCH];
    int tid = threadIdx.x;
    for (int i = tid; i < ED*ZCH; i += 256) { sqw[i] = qw[i]; slw[i] = lw[i]; }
    __syncthreads();
    int p = blockIdx.x * 256 + tid;
    int b = p >> 10, rem = p & 1023;
    float q[ED], l[ED];
    #pragma unroll
    for (int e = 0; e < ED; e++) { q[e] = qb[e]; l[e] = lb[e]; }
    size_t base = (size_t)b * ZCH * 1024 + rem;
    for (int c = 0; c < ZCH; c++) {
        float a  = zt[base + (size_t)c * 1024];
        float zl = zlp[base + (size_t)c * 1024];
        #pragma unroll
        for (int e = 0; e < ED; e++) {
            q[e] = fmaf(a,  sqw[e*ZCH + c], q[e]);
            l[e] = fmaf(zl, slw[e*ZCH + c], l[e]);
        }
    }
    float zz = 0.f;
    #pragma unroll
    for (int e = 0; e < ED; e++) { g_z[(size_t)p*ED + e] = q[e]; zz = fmaf(q[e], q[e], zz); }
    g_zz[p] = zz;
    #pragma unroll
    for (int e = 0; e < ED; e++) {
        size_t oi = (size_t)b * ED * 1024 + (size_t)e * 1024 + rem;
        out_zl[oi] = l[e];
        g_zl[oi]  = l[e];
    }
}

// exact fp32 VQ distance GEMM (K=16) + per-tile argmin partials
__global__ void __launch_bounds__(256, 2) k_vqgemm(const float* __restrict__ Bm)
{
    __shared__ float As[16][128];
    __shared__ float Bs[16][128];
    const float* Am = g_z;
    const int n0 = blockIdx.x * 128;
    const int m0 = blockIdx.y * 128;
    const int tid = threadIdx.x;
    const int tx = tid & 15, ty = tid >> 4;
    float acc[8][8];
    #pragma unroll
    for (int i = 0; i < 8; i++)
        #pragma unroll
        for (int j = 0; j < 8; j++) acc[i][j] = 0.f;

    {
        #pragma unroll
        for (int q = 0; q < 2; q++) {
            int e4 = tid + q * 256;
            int row = e4 >> 2;
            int kq = (e4 & 3) << 2;
            float4 va = *(const float4*)(Am + (size_t)(m0 + row) * 16 + kq);
            As[kq+0][row] = va.x; As[kq+1][row] = va.y; As[kq+2][row] = va.z; As[kq+3][row] = va.w;
            float4 vb = *(const float4*)(Bm + (size_t)(n0 + row) * 16 + kq);
            Bs[kq+0][row] = vb.x; Bs[kq+1][row] = vb.y; Bs[kq+2][row] = vb.z; Bs[kq+3][row] = vb.w;
        }
        __syncthreads();
        #pragma unroll
        for (int k = 0; k < 16; k++) {
            float a[8], bb[8];
            #pragma unroll
            for (int i = 0; i < 8; i++) a[i] = As[k][ty*8 + i];
            #pragma unroll
            for (int j = 0; j < 8; j++) bb[j] = Bs[k][tx*8 + j];
            #pragma unroll
            for (int i = 0; i < 8; i++)
                #pragma unroll
                for (int j = 0; j < 8; j++) acc[i][j] = fmaf(a[i], bb[j], acc[i][j]);
        }
        __syncthreads();
    }

    float nv[8];
    #pragma unroll
    for (int j = 0; j < 8; j++) nv[j] = g_cnorm[n0 + tx*8 + j];
    float lv[8]; int li[8];
    #pragma unroll
    for (int i = 0; i < 8; i++) {
        int gr = m0 + ty*8 + i;
        float zz = g_zz[gr];
        float v[8];
        #pragma unroll
        for (int j = 0; j < 8; j++) v[j] = zz + nv[j] - 2.f * acc[i][j];
        float best = v[0]; int bidx = n0 + tx*8;
        #pragma unroll
        for (int j = 1; j < 8; j++) if (v[j] < best) { best = v[j]; bidx = n0 + tx*8 + j; }
        lv[i] = best; li[i] = bidx;
    }
    __syncthreads();
    float* sval = &As[0][0];
    int*   sidx = (int*)&Bs[0][0];
    #pragma unroll
    for (int i = 0; i < 8; i++) { int row = ty*8 + i; sval[row*16 + tx] = lv[i]; sidx[row*16 + tx] = li[i]; }
    __syncthreads();
    if (tid < 128) {
        float bv = sval[tid*16]; int bi = sidx[tid*16];
        #pragma unroll
        for (int t = 1; t < 16; t++) {
            float v = sval[tid*16 + t]; int ii = sidx[tid*16 + t];
            if (v < bv || (v == bv && ii < bi)) { bv = v; bi = ii; }
        }
        size_t o = (size_t)(m0 + tid) * NBT + blockIdx.x;
        g_pv2[o] = bv; g_pi2[o] = bi;
    }
}

template<bool ISMAX>
__global__ void k_argreduce(float* __restrict__ outf) {
    int row = blockIdx.x, t = threadIdx.x;
    __shared__ float sv[128];
    __shared__ int   si[128];
    const float* pv = ISMAX ? g_pv : g_pv2;
    const int*   pi = ISMAX ? g_pi : g_pi2;
    sv[t] = pv[(size_t)row * NBT + t];
    si[t] = pi[(size_t)row * NBT + t];
    __syncthreads();
    for (int s = 64; s; s >>= 1) {
        if (t < s) {
            float v2 = sv[t+s]; int i2 = si[t+s];
            bool better = ISMAX ? (v2 > sv[t]) : (v2 < sv[t]);
            if (better || (v2 == sv[t] && i2 < si[t])) { sv[t] = v2; si[t] = i2; }
        }
        __syncthreads();
    }
    if (t == 0) {
        if (ISMAX) g_topidx[row] = si[0];
        else { g_vqidx[row] = si[0]; outf[row] = (float)si[0]; }
    }
}

__global__ void k_zhq(const float* __restrict__ cb, float* __restrict__ out_zhq) {
    int o = blockIdx.x * 256 + threadIdx.x;
    int b = o >> 14, e = (o >> 10) & 15, rem = o & 1023;
    int p = b * 1024 + rem;
    out_zhq[o] = cb[(size_t)g_vqidx[p] * ED + e];
}

__global__ void __launch_bounds__(256) k_pcn1(const float* __restrict__ w1, const float* __restrict__ b1) {
    __shared__ float img[8 * 1024];
    __shared__ float wt[ED * 49];
    int b = blockIdx.x >> 6, oc = blockIdx.x & 63;
    int tid = threadIdx.x;
    for (int i = tid; i < ED * 49; i += 256) wt[i] = w1[(size_t)oc * ED * 49 + i];
    float bias = b1[oc];
    float acc[4];
    #pragma unroll
    for (int k = 0; k < 4; k++) acc[k] = bias;
    for (int half = 0; half < 2; half++) {
        __syncthreads();
        for (int i = tid; i < 8192; i += 256) img[i] = g_zl[(size_t)b * 16384 + half * 8192 + i];
        __syncthreads();
        #pragma unroll
        for (int k = 0; k < 4; k++) {
            int p = tid + k * 256;
            int y = p >> 5, x = p & 31;
            for (int ic = 0; ic < 8; ic++) {
                const float* ib = img + ic * 1024;
                const float* wb = wt + (half * 8 + ic) * 49;
                #pragma unroll
                for (int ky = 0; ky < 7; ky++) {
                    int yy = y + ky - 3;
                    if (yy < 0 || yy >= 32) continue;
                    #pragma unroll
                    for (int kx = 0; kx < 7; kx++) {
                        int xx = x + kx - 3;
                        if (xx < 0 || xx >= 32) continue;
                        acc[k] = fmaf(ib[yy*32 + xx], wb[ky*7 + kx], acc[k]);
                    }
                }
            }
        }
    }
    #pragma unroll
    for (int k = 0; k < 4; k++) {
        int p = tid + k * 256;
        g_h[(size_t)(b * 1024 + p) * PCH + oc] = fmaxf(acc[k], 0.f);
    }
}

// ---------------- bf16 split conversion (K-interleaved) ----------------
__global__ void k_cvt_h() {
    int i = blockIdx.x * 256 + threadIdx.x;      // NPOS*PCH
    int row = i >> 6, c = i & 63;
    float x = g_h[i];
    __nv_bfloat16 hi = __float2bfloat16(x);
    __nv_bfloat16 lo = __float2bfloat16(x - __bfloat162float(hi));
    size_t b = (size_t)row * KSPLIT + c;
    g_Ab[b] = hi; g_Ab[b + 64] = hi; g_Ab[b + 128] = lo;
}
__global__ void k_cvt_w(const float* __restrict__ w) {
    int i = blockIdx.x * 256 + threadIdx.x;      // NEMB*PCH
    int row = i >> 6, c = i & 63;
    float x = w[i];
    __nv_bfloat16 hi = __float2bfloat16(x);
    __nv_bfloat16 lo = __float2bfloat16(x - __bfloat162float(hi));
    size_t b = (size_t)row * KSPLIT + c;
    g_Bb[b] = hi; g_Bb[b + 64] = lo; g_Bb[b + 128] = hi;
}

// ---------------- mma.sync logits GEMM ----------------
// C[m][n] = sum_k A'[m][k] * B'[n][k] + bias[n];  M=4096, N=16384, K=192
// CTA: 128x128 tile, 256 thr (8 warps as 4x2; warp tile 32x64)
#define SSTR 72
__global__ void __launch_bounds__(256) k_mmagemm(const float* __restrict__ bias,
                                                 float* __restrict__ C)
{
    __shared__ __align__(16) __nv_bfloat16 sA[128 * SSTR];
    __shared__ __align__(16) __nv_bfloat16 sB[128 * SSTR];
    const int n0 = blockIdx.x * 128, m0 = blockIdx.y * 128;
    const int tid = threadIdx.x;
    const int warp = tid >> 5, lane = tid & 31;
    const int wr = warp >> 1, wc = warp & 1;
    const uint32_t sAu = smem_to_u32(sA), sBu = smem_to_u32(sB);

    float acc[2][8][4];
    #pragma unroll
    for (int i = 0; i < 2; i++)
        #pragma unroll
        for (int j = 0; j < 8; j++)
            #pragma unroll
            for (int f = 0; f < 4; f++) acc[i][j][f] = 0.f;

    // ldmatrix source addresses (fixed per thread)
    const uint32_t aAddrBase = sAu + (uint32_t)(((wr*32 + (lane & 15)) * SSTR + (lane >> 4) * 8) * 2);
    const int bRow = wc*64 + ((lane & 7) | ((lane >> 4) << 3));
    const int bKoff = ((lane >> 3) & 1) * 8;
    const uint32_t bAddrBase = sBu + (uint32_t)((bRow * SSTR + bKoff) * 2);

    #pragma unroll
    for (int kc = 0; kc < 3; kc++) {
        // stage 128x64 bf16 tiles of A' and B'
        #pragma unroll
        for (int t = 0; t < 4; t++) {
            int e = tid + t * 256;            // 0..1023
            int row = e >> 3, seg = e & 7;
            *(float4*)&sA[row * SSTR + seg * 8] =
                *(const float4*)(g_Ab + (size_t)(m0 + row) * KSPLIT + kc * 64 + seg * 8);
            *(float4*)&sB[row * SSTR + seg * 8] =
                *(const float4*)(g_Bb + (size_t)(n0 + row) * KSPLIT + kc * 64 + seg * 8);
        }
        __syncthreads();
        #pragma unroll
        for (int k16 = 0; k16 < 4; k16++) {
            uint32_t a[2][4];
            #pragma unroll
            for (int i = 0; i < 2; i++)
                ldsm_x4(a[i][0], a[i][1], a[i][2], a[i][3],
                        aAddrBase + (uint32_t)((i*16*SSTR + k16*16) * 2));
            uint32_t b[8][2];
            #pragma unroll
            for (int jj = 0; jj < 4; jj++)
                ldsm_x4(b[2*jj][0], b[2*jj][1], b[2*jj+1][0], b[2*jj+1][1],
                        bAddrBase + (uint32_t)((jj*16*SSTR + k16*16) * 2));
            #pragma unroll
            for (int i = 0; i < 2; i++)
                #pragma unroll
                for (int j = 0; j < 8; j++)
                    mma16816(acc[i][j], a[i], b[j]);
        }
        __syncthreads();
    }

    // epilogue: bias add, store C, per-row argmax candidates
    const int q = lane & 3, quad = lane >> 2;
    float2 bv[8];
    #pragma unroll
    for (int j = 0; j < 8; j++)
        bv[j] = *(const float2*)(bias + n0 + wc*64 + j*8 + 2*q);

    float* sval = (float*)sA;      // [128][8]
    int*   sidx = (int*)sB;
    #pragma unroll
    for (int i = 0; i < 2; i++) {
        #pragma unroll
        for (int half = 0; half < 2; half++) {
            int r = wr*32 + i*16 + half*8 + quad;
            float best = -3.4e38f; int bi = 0;
            #pragma unroll
            for (int j = 0; j < 8; j++) {
                int col = n0 + wc*64 + j*8 + 2*q;
                float v0 = acc[i][j][half*2 + 0] + bv[j].x;
                float v1 = acc[i][j][half*2 + 1] + bv[j].y;
                *(float2*)(C + (size_t)(m0 + r) * NEMB + col) = make_float2(v0, v1);
                if (v0 > best || (v0 == best && col < bi)) { best = v0; bi = col; }
                if (v1 > best || (v1 == best && col + 1 < bi)) { best = v1; bi = col + 1; }
            }
            sval[r*8 + wc*4 + q] = best;
            sidx[r*8 + wc*4 + q] = bi;
        }
    }
    __syncthreads();
    if (tid < 128) {
        float bvv = sval[tid*8]; int bii = sidx[tid*8];
        #pragma unroll
        for (int s = 1; s < 8; s++) {
            float v = sval[tid*8 + s]; int ii = sidx[tid*8 + s];
            if (v > bvv || (v == bvv && ii < bii)) { bvv = v; bii = ii; }
        }
        g_pv[(size_t)(m0 + tid) * NBT + blockIdx.x] = bvv;
        g_pi[(size_t)(m0 + tid) * NBT + blockIdx.x] = bii;
    }
}

// ---------------- decoder kernels ----------------
__global__ void __launch_bounds__(256) k_pq(const float* __restrict__ cb,
                                            const float* __restrict__ pqw,
                                            const float* __restrict__ pqb) {
    __shared__ float spw[ZCH * ED];
    int tid = threadIdx.x;
    for (int i = tid; i < ZCH * ED; i += 256) spw[i] = pqw[i];
    __syncthreads();
    int p = blockIdx.x * 256 + tid;
    int b = p >> 10, rem = p & 1023;
    float code[ED];
    int ci = g_topidx[p];
    #pragma unroll
    for (int e = 0; e < ED; e++) code[e] = cb[(size_t)ci * ED + e];
    for (int zc = 0; zc < ZCH; zc++) {
        float a = pqb[zc];
        #pragma unroll
        for (int e = 0; e < ED; e++) a = fmaf(spw[zc*ED + e], code[e], a);
        g_dcin[(size_t)b * ZCH * 1024 + (size_t)zc * 1024 + rem] = a;
    }
}

__global__ void __launch_bounds__(256) k_dec1(const float* __restrict__ w, const float* __restrict__ bias) {
    __shared__ float slice[1024];
    int b = blockIdx.x >> 6, oc = blockIdx.x & 63;
    int tid = threadIdx.x;
    float bb = bias[oc];
    float acc[4];
    #pragma unroll
    for (int k = 0; k < 4; k++) acc[k] = bb;
    for (int ic = 0; ic < ZCH; ic++) {
        __syncthreads();
        for (int i = tid; i < 1024; i += 256) slice[i] = g_dcin[(size_t)b * 65536 + (size_t)ic * 1024 + i];
        __syncthreads();
        float w9[9];
        #pragma unroll
        for (int j = 0; j < 9; j++) w9[j] = w[((size_t)oc * ZCH + ic) * 9 + j];
        #pragma unroll
        for (int k = 0; k < 4; k++) {
            int p = tid + k * 256;
            int y = p >> 5, x = p & 31;
            #pragma unroll
            for (int ky = 0; ky < 3; ky++) {
                int yy = y + ky - 1;
                if (yy < 0 || yy >= 32) continue;
                #pragma unroll
                for (int kx = 0; kx < 3; kx++) {
                    int xx = x + kx - 1;
                    if (xx < 0 || xx >= 32) continue;
                    acc[k] = fmaf(slice[yy*32 + xx], w9[ky*3 + kx], acc[k]);
                }
            }
        }
    }
    #pragma unroll
    for (int k = 0; k < 4; k++)
        g_d0[(size_t)b * 65536 + (size_t)oc * 1024 + tid + k * 256] = fmaxf(acc[k], 0.f);
}

__global__ void __launch_bounds__(256) k_fuse(const float* __restrict__ ff,
                                              const float* __restrict__ fw,
                                              const float* __restrict__ fb,
                                              const void* __restrict__ wscalar) {
    __shared__ float slice[64 * 64];
    int b = blockIdx.x >> 6, oc = blockIdx.x & 63;
    int tid = threadIdx.x;
    int ty0 = (tid >> 4) * 4, tx0 = (tid & 15) * 4;
    float acc[4][4];
    float bb = fb[oc];
    #pragma unroll
    for (int i = 0; i < 4; i++)
        #pragma unroll
        for (int j = 0; j < 4; j++) acc[i][j] = bb;
    for (int ic = 0; ic < ZCH; ic++) {
        __syncthreads();
        for (int i = tid; i < 4096; i += 256)
            slice[i] = ff[(size_t)b * ZCH * 4096 + (size_t)ic * 4096 + i];
        __syncthreads();
        float w9[9];
        #pragma unroll
        for (int j = 0; j < 9; j++) w9[j] = fw[((size_t)oc * ZCH + ic) * 9 + j];
        float r[6][6];
        #pragma unroll
        for (int yy = 0; yy < 6; yy++)
            #pragma unroll
            for (int xx = 0; xx < 6; xx++) {
                int Y = ty0 + yy - 1, X = tx0 + xx - 1;
                r[yy][xx] = (Y >= 0 && Y < 64 && X >= 0 && X < 64) ? slice[Y*64 + X] : 0.f;
            }
        #pragma unroll
        for (int i = 0; i < 4; i++)
            #pragma unroll
            for (int j = 0; j < 4; j++)
                #pragma unroll
                for (int ky = 0; ky < 3; ky++)
                    #pragma unroll
                    for (int kx = 0; kx < 3; kx++)
                        acc[i][j] = fmaf(r[i+ky][j+kx], w9[ky*3 + kx], acc[i][j]);
    }
    float wf = get_w(wscalar);
    #pragma unroll
    for (int i = 0; i < 4; i++)
        #pragma unroll
        for (int j = 0; j < 4; j++) {
            int Y = ty0 + i, X = tx0 + j;
            float v = g_d0[(size_t)b * 65536 + (size_t)oc * 1024 + (Y>>1)*32 + (X>>1)] + wf * acc[i][j];
            g_t[(size_t)b * ZCH * 4096 + (size_t)oc * 4096 + Y*64 + X] = fmaxf(v, 0.f);
        }
}

__global__ void __launch_bounds__(256) k_dec2(const float* __restrict__ w2,
                                              const float* __restrict__ b2,
                                              float* __restrict__ out_dec) {
    __shared__ float rows[3][64];
    int b = blockIdx.x >> 6;
    int Y0 = (blockIdx.x & 63) * 2;
    int tid = threadIdx.x;
    int Y = Y0 + (tid >> 7);
    int X = tid & 127;
    int m = Y0 >> 1;
    float acc = b2[0];
    for (int c = 0; c < ZCH; c++) {
        __syncthreads();
        for (int i = tid; i < 192; i += 256) {
            int rr = i / 64, cc = i % 64;
            int tr = m - 1 + rr;
            rows[rr][cc] = (tr >= 0 && tr < 64)
                ? g_t[(size_t)b * ZCH * 4096 + (size_t)c * 4096 + tr*64 + cc] : 0.f;
        }
        __syncthreads();
        float w9[9];
        #pragma unroll
        for (int j = 0; j < 9; j++) w9[j] = w2[(size_t)c * 9 + j];
        #pragma unroll
        for (int ky = 0; ky < 3; ky++) {
            int Yt = Y + ky - 1;
            if (Yt < 0 || Yt > 127) continue;
            int rr = (Yt >> 1) - (m - 1);
            #pragma unroll
            for (int kx = 0; kx < 3; kx++) {
                int Xt = X + kx - 1;
                if (Xt < 0 || Xt > 127) continue;
                acc = fmaf(rows[rr][Xt >> 1], w9[ky*3 + kx], acc);
            }
        }
    }
    out_dec[(size_t)b * 16384 + Y * 128 + X] = acc;
}

extern "C" void kernel_launch(void* const* d_in, const int* in_sizes, int n_in,
                              void* d_out, int out_size) {
    const float* z_t      = (const float*)d_in[0];
    const float* z_l_pre  = (const float*)d_in[1];
    const float* fuse_feat= (const float*)d_in[2];
    const void*  wptr     = d_in[3];
    const float* quant_w  = (const float*)d_in[4];
    const float* quant_b  = (const float*)d_in[5];
    const float* codebook = (const float*)d_in[6];
    const float* lrq_w    = (const float*)d_in[7];
    const float* lrq_b    = (const float*)d_in[8];
    const float* pcn_w1   = (const float*)d_in[9];
    const float* pcn_b1   = (const float*)d_in[10];
    const float* pcn_w2   = (const float*)d_in[11];
    const float* pcn_b2   = (const float*)d_in[12];
    const float* pq_w     = (const float*)d_in[13];
    const float* pq_b     = (const float*)d_in[14];
    const float* dec_w1   = (const float*)d_in[15];
    const float* dec_b1   = (const float*)d_in[16];
    const float* fuse_w   = (const float*)d_in[17];
    const float* fuse_b   = (const float*)d_in[18];
    const float* dec_w2   = (const float*)d_in[19];
    const float* dec_b2   = (const float*)d_in[20];

    float* out = (float*)d_out;
    float* out_logits = out;
    float* out_zl     = out_logits + (size_t)NPOS * NEMB;
    float* out_tgt    = out_zl + (size_t)BATCH * ED * 1024;
    float* out_zhq    = out_tgt + NPOS;
    float* out_dec    = out_zhq + (size_t)BATCH * ED * 1024;

    k_cvt_w<<<(NEMB*PCH)/256, 256>>>(pcn_w2);
    k_cnorm<<<NEMB/256, 256>>>(codebook);
    k_quant_lrq<<<NPOS/256, 256>>>(z_t, z_l_pre, quant_w, quant_b, lrq_w, lrq_b, out_zl);

    // frozen HQ path: exact fp32 VQ argmin + gather
    k_vqgemm<<<dim3(NBT, NPOS/128), 256>>>(codebook);
    k_argreduce<false><<<NPOS, 128>>>(out_tgt);
    k_zhq<<<(BATCH*ED*1024)/256, 256>>>(codebook, out_zhq);

    // LR path: pixelcnn -> bf16 split -> mma.sync logits GEMM -> argmax
    k_pcn1<<<BATCH*PCH, 256>>>(pcn_w1, pcn_b1);
    k_cvt_h<<<(NPOS*PCH)/256, 256>>>();
    k_mmagemm<<<dim3(NBT, NPOS/128), 256>>>(pcn_b2, out_logits);
    k_argreduce<true><<<NPOS, 128>>>(nullptr);

    // decoder
    k_pq<<<NPOS/256, 256>>>(codebook, pq_w, pq_b);
    k_dec1<<<BATCH*ZCH, 256>>>(dec_w1, dec_b1);
    k_fuse<<<BATCH*ZCH, 256>>>(fuse_feat, fuse_w, fuse_b, wptr);
    k_dec2<<<BATCH*64, 256>>>(dec_w2, dec_b2, out_dec);
}